// round 11
// baseline (speedup 1.0000x reference)
#include <cuda_runtime.h>
#include <cuda_fp16.h>
#include <math.h>
#include <stdint.h>

// ---------------------------------------------------------------------------
// LinOSS layer: B=16, N=4096, q=256 on sm_103
// fp16 operands pre-converted once; GEMMs: cp.async 3-stage (BK=32) HMMA,
// full-width N tiling (TM=64, TN=256) so activations stream through L2 once.
//   u16 = fp16(u); W*16 = fp16(W*)
//   Bu16 = fp16(u16 @ WB16^T + bB)
//   y    = IM scan over Bu16 (chunked 3-pass, parallel KS combine); y + y16
//   h    = y16@WC16^T + u16@WD16^T + bC + bD; g=gelu(h); out=g*sigmoid(g)+u16
// Output: [out | y]
// ---------------------------------------------------------------------------

namespace {
constexpr int kB = 16;
constexpr int kN = 4096;
constexpr int kQ = 256;
constexpr int kM = kB * kN;                 // 65536
constexpr float kDT = 1.0f / 4096.0f;
constexpr int kNChunk = 64;
constexpr int kCLen = kN / kNChunk;         // 64

constexpr int TM = 64, TN = 256, BK = 32;   // CTA tile, K-chunk (fp16)
constexpr int SSTR = 40;                    // smem row stride in halves (80 B)
constexpr int A_PL_BYTES = TM * SSTR * 2;   // 5120
constexpr int B_PL_BYTES = TN * SSTR * 2;   // 20480
constexpr int STAGE_BYTES = A_PL_BYTES + B_PL_BYTES;  // 25600
constexpr int NSTAGE = 3;
constexpr int SMEM_BYTES = NSTAGE * STAGE_BYTES;      // 76800
}  // namespace

// Device scratch (static; no cudaMalloc allowed)
__device__ __half g_Bu16[(size_t)kM * kQ];
__device__ float2 g_end[kB * kNChunk * kQ];
__device__ float2 g_init[kB * kNChunk * kQ];
__device__ __half g_u16[(size_t)kM * kQ];
__device__ __half g_y16[(size_t)kM * kQ];
__device__ __half g_WB16[kQ * kQ];
__device__ __half g_WC16[kQ * kQ];
__device__ __half g_WD16[kQ * kQ];

// ---------------------------------------------------------------------------
// helpers
// ---------------------------------------------------------------------------
__device__ __forceinline__ uint32_t smem_u32(const void* p) {
    uint32_t a;
    asm("{ .reg .u64 t; cvta.to.shared.u64 t, %1; cvt.u32.u64 %0, t; }" : "=r"(a) : "l"(p));
    return a;
}
__device__ __forceinline__ uint32_t packh(float a, float b) {
    __half2 h = __floats2half2_rn(a, b);
    uint32_t u; memcpy(&u, &h, 4); return u;
}
__device__ __forceinline__ void ldsm4(uint32_t (&r)[4], uint32_t addr) {
    asm volatile("ldmatrix.sync.aligned.m8n8.x4.shared.b16 {%0,%1,%2,%3}, [%4];"
                 : "=r"(r[0]), "=r"(r[1]), "=r"(r[2]), "=r"(r[3]) : "r"(addr));
}
__device__ __forceinline__ void mma16816(float* c, const uint32_t* a, const uint32_t* b) {
    asm volatile(
        "mma.sync.aligned.m16n8k16.row.col.f32.f16.f16.f32 "
        "{%0,%1,%2,%3}, {%4,%5,%6,%7}, {%8,%9}, {%0,%1,%2,%3};"
        : "+f"(c[0]), "+f"(c[1]), "+f"(c[2]), "+f"(c[3])
        : "r"(a[0]), "r"(a[1]), "r"(a[2]), "r"(a[3]), "r"(b[0]), "r"(b[1]));
}
#define CP_COMMIT() asm volatile("cp.async.commit_group;" ::: "memory")
#define CP_WAIT1()  asm volatile("cp.async.wait_group 1;" ::: "memory")

// Issue one stage: A tile (64 x 32 fp16) + B tile (256 x 32 fp16).
// A: 256 transfers (1/thread); B: 1024 transfers (4/thread).
__device__ __forceinline__ void cpa_stage(uint32_t sb, const __half* __restrict__ aSrc,
                                          const __half* __restrict__ bSrc, int tid) {
    {
        int r = tid >> 2, j = tid & 3;
        const __half* g = aSrc + (size_t)r * kQ + j * 8;
        uint32_t s = sb + (uint32_t)(r * 80 + j * 16);
        asm volatile("cp.async.ca.shared.global [%0], [%1], 16;" :: "r"(s), "l"(g));
    }
#pragma unroll
    for (int k = 0; k < 4; k++) {
        int t = tid + k * 256;             // 0..1023
        int r = t >> 2, j = t & 3;
        const __half* g = bSrc + (size_t)r * kQ + j * 8;
        uint32_t s = sb + A_PL_BYTES + (uint32_t)(r * 80 + j * 16);
        asm volatile("cp.async.ca.shared.global [%0], [%1], 16;" :: "r"(s), "l"(g));
    }
}

// MMA over one resident stage: warp tile 32(M) x 64(N).
__device__ __forceinline__ void mma_stage(uint32_t sb, float (&acc)[2][8][4],
                                          int lane, int wm, int wn) {
    const int g = lane >> 3, l = lane & 7;
#pragma unroll
    for (int k16 = 0; k16 < 2; k16++) {
        uint32_t afrag[2][4];
        const int acol = k16 * 16 + (g >> 1) * 8;
#pragma unroll
        for (int mt = 0; mt < 2; mt++) {
            const int arow = wm + mt * 16 + (g & 1) * 8 + l;
            ldsm4(afrag[mt], sb + (uint32_t)(arow * SSTR + acol) * 2);
        }
        const int bcol = k16 * 16 + (g & 1) * 8;
#pragma unroll
        for (int np = 0; np < 4; np++) {
            const int brow = wn + np * 16 + (g >> 1) * 8 + l;
            uint32_t bfrag[4];
            ldsm4(bfrag, sb + A_PL_BYTES + (uint32_t)(brow * SSTR + bcol) * 2);
#pragma unroll
            for (int mt = 0; mt < 2; mt++) {
#pragma unroll
                for (int nt = 0; nt < 2; nt++) {
                    mma16816(acc[mt][np * 2 + nt], afrag[mt], &bfrag[nt * 2]);
                }
            }
        }
    }
}

// ---------------------------------------------------------------------------
// Converter: u (16M elems) + WB/WC/WD (64K each), one kernel.
// ---------------------------------------------------------------------------
__global__ __launch_bounds__(256) void k_cvt(const float* __restrict__ u,
                                             const float* __restrict__ wb,
                                             const float* __restrict__ wc,
                                             const float* __restrict__ wd) {
    const int uN = kM * kQ / 4;
    const int per = kQ * kQ / 4;
    int i = blockIdx.x * blockDim.x + threadIdx.x;
    const float* s;
    __half* d;
    int j;
    if (i < uN) { s = u; d = g_u16; j = i; }
    else {
        int w = i - uN;
        s = (w < per) ? wb : (w < 2 * per ? wc : wd);
        d = (w < per) ? g_WB16 : (w < 2 * per ? g_WC16 : g_WD16);
        j = w % per;
    }
    float4 v = reinterpret_cast<const float4*>(s)[j];
    uint2 o; o.x = packh(v.x, v.y); o.y = packh(v.z, v.w);
    reinterpret_cast<uint2*>(d)[j] = o;
}

// ---------------------------------------------------------------------------
// GEMM1: g_Bu16 = fp16(u16 @ WB16^T + bias)   grid = kM/TM = 1024
// ---------------------------------------------------------------------------
__global__ __launch_bounds__(256, 2) void k_mm_bu(const float* __restrict__ bias)
{
    extern __shared__ __half smem[];
    const int tid = threadIdx.x;
    const int tileRow = blockIdx.x * TM;
    const int lane = tid & 31, wid = tid >> 5;
    const int wm = (wid & 1) * 32, wn = (wid >> 1) * 64;
    const uint32_t smb = smem_u32(smem);

    float acc[2][8][4];
#pragma unroll
    for (int a = 0; a < 2; a++)
#pragma unroll
        for (int b = 0; b < 8; b++)
#pragma unroll
            for (int c = 0; c < 4; c++) acc[a][b][c] = 0.0f;

    const __half* aBase = g_u16 + (size_t)tileRow * kQ;
    const __half* bBase = g_WB16;

    cpa_stage(smb, aBase, bBase, tid); CP_COMMIT();
    cpa_stage(smb + STAGE_BYTES, aBase + BK, bBase + BK, tid); CP_COMMIT();

    constexpr int C = kQ / BK;     // 8
    for (int c = 0; c < C; c++) {
        CP_WAIT1();
        __syncthreads();
        if (c + 2 < C)
            cpa_stage(smb + ((c + 2) % NSTAGE) * STAGE_BYTES,
                      aBase + (c + 2) * BK, bBase + (c + 2) * BK, tid);
        CP_COMMIT();
        mma_stage(smb + (c % NSTAGE) * STAGE_BYTES, acc, lane, wm, wn);
    }

    const int r0 = tileRow + wm + (lane >> 2);
#pragma unroll
    for (int mt = 0; mt < 2; mt++) {
        const int rr = r0 + mt * 16;
#pragma unroll
        for (int nt = 0; nt < 8; nt++) {
            const int cc = wn + nt * 8 + (lane & 3) * 2;
            const float b0 = bias[cc], b1 = bias[cc + 1];
            uint32_t lo = packh(acc[mt][nt][0] + b0, acc[mt][nt][1] + b1);
            uint32_t hi = packh(acc[mt][nt][2] + b0, acc[mt][nt][3] + b1);
            *reinterpret_cast<uint32_t*>(&g_Bu16[(size_t)rr * kQ + cc]) = lo;
            *reinterpret_cast<uint32_t*>(&g_Bu16[(size_t)(rr + 8) * kQ + cc]) = hi;
        }
    }
}

// ---------------------------------------------------------------------------
// GEMM2: h = y16@WC16^T + u16@WD16^T + bC + bD; gelu+glu epilogue,
// residual from u16.   grid = kM/TM = 1024
// ---------------------------------------------------------------------------
__global__ __launch_bounds__(256, 2) void k_mm_out(
    const float* __restrict__ bC, const float* __restrict__ bD,
    float* __restrict__ Out)
{
    extern __shared__ __half smem[];
    const int tid = threadIdx.x;
    const int tileRow = blockIdx.x * TM;
    const int lane = tid & 31, wid = tid >> 5;
    const int wm = (wid & 1) * 32, wn = (wid >> 1) * 64;
    const uint32_t smb = smem_u32(smem);

    float acc[2][8][4];
#pragma unroll
    for (int a = 0; a < 2; a++)
#pragma unroll
        for (int b = 0; b < 8; b++)
#pragma unroll
            for (int c = 0; c < 4; c++) acc[a][b][c] = 0.0f;

    constexpr int C = 2 * kQ / BK;   // 16
    auto aPtr = [&](int n) -> const __half* {
        return (n < C / 2 ? g_y16 : g_u16) + (size_t)tileRow * kQ + (n & (C / 2 - 1)) * BK;
    };
    auto bPtr = [&](int n) -> const __half* {
        return (n < C / 2 ? g_WC16 : g_WD16) + (n & (C / 2 - 1)) * BK;
    };

    cpa_stage(smb, aPtr(0), bPtr(0), tid); CP_COMMIT();
    cpa_stage(smb + STAGE_BYTES, aPtr(1), bPtr(1), tid); CP_COMMIT();

    for (int c = 0; c < C; c++) {
        CP_WAIT1();
        __syncthreads();
        if (c + 2 < C)
            cpa_stage(smb + ((c + 2) % NSTAGE) * STAGE_BYTES, aPtr(c + 2), bPtr(c + 2), tid);
        CP_COMMIT();
        mma_stage(smb + (c % NSTAGE) * STAGE_BYTES, acc, lane, wm, wn);
    }

    const int r0 = tileRow + wm + (lane >> 2);
#pragma unroll
    for (int mt = 0; mt < 2; mt++) {
        const int rr = r0 + mt * 16;
#pragma unroll
        for (int nt = 0; nt < 8; nt++) {
            const int cc = wn + nt * 8 + (lane & 3) * 2;
            const float b0 = bC[cc] + bD[cc], b1 = bC[cc + 1] + bD[cc + 1];
#pragma unroll
            for (int half = 0; half < 2; half++) {
                const int row = rr + half * 8;
                float h0 = acc[mt][nt][half * 2 + 0] + b0;
                float h1 = acc[mt][nt][half * 2 + 1] + b1;
                __half2 uh = *reinterpret_cast<const __half2*>(&g_u16[(size_t)row * kQ + cc]);
                float2 uv = __half22float2(uh);
                float g0 = 0.5f * h0 * (1.0f + erff(h0 * 0.70710678118654752f));
                float g1 = 0.5f * h1 * (1.0f + erff(h1 * 0.70710678118654752f));
                float o0 = fmaf(g0, 1.0f / (1.0f + __expf(-g0)), uv.x);
                float o1 = fmaf(g1, 1.0f / (1.0f + __expf(-g1)), uv.y);
                float2 w; w.x = o0; w.y = o1;
                *reinterpret_cast<float2*>(&Out[(size_t)row * kQ + cc]) = w;
            }
        }
    }
}

// ---------------------------------------------------------------------------
// Scan pass A: per-chunk end states (fp16 Bu reads)
// ---------------------------------------------------------------------------
__global__ __launch_bounds__(256) void k_scan_ends(const float* __restrict__ A)
{
    int idx = blockIdx.x * blockDim.x + threadIdx.x;
    int qi = idx & (kQ - 1);
    int c  = (idx >> 8) & (kNChunk - 1);
    int b  = idx >> 14;

    float av  = A[qi];
    float s   = 1.0f / (1.0f + kDT * kDT * av);
    float dts = kDT * s;
    float dsa = dts * av;

    const __half* p = g_Bu16 + ((size_t)(b * kN + c * kCLen)) * kQ + qi;
    float x = 0.0f, z = 0.0f;
#pragma unroll 4
    for (int n = 0; n < kCLen; n++) {
        float bu = __half2float(p[(size_t)n * kQ]);
        float fx = dts * bu;
        float xn = fmaf(s, x, fmaf(-dsa, z, fx));
        float zn = fmaf(dts, x, fmaf(s, z, kDT * fx));
        x = xn; z = zn;
    }
    g_end[idx] = make_float2(x, z);
}

// ---------------------------------------------------------------------------
// Scan pass B: PARALLEL chunk-prefix combine (Kogge-Stone affine scan).
// Per-chunk linear part P_chunk = M^kCLen (pre-squared 6x from M).
// ---------------------------------------------------------------------------
__global__ __launch_bounds__(256) void k_scan_combine(const float* __restrict__ A)
{
    __shared__ float2 sb[256];
    const int tid = threadIdx.x;
    const int c = tid & (kNChunk - 1);                 // chunk 0..63
    const int pairIdx = blockIdx.x * 4 + (tid >> 6);   // (b,qi) pair
    const int qi = pairIdx & (kQ - 1);
    const int b  = pairIdx >> 8;

    float av  = A[qi];
    float s   = 1.0f / (1.0f + kDT * kDT * av);
    float dts = kDT * s;
    float dsa = dts * av;

    float p00 = s, p01 = -dsa, p10 = dts, p11 = s;
#pragma unroll
    for (int k = 0; k < 6; k++) {          // M -> M^64 = P_chunk
        float t   = p00 + p11;
        float bc  = p01 * p10;
        float n00 = fmaf(p00, p00, bc);
        float n01 = p01 * t;
        float n10 = p10 * t;
        float n11 = fmaf(p11, p11, bc);
        p00 = n00; p01 = n01; p10 = n10; p11 = n11;
    }

    const int gbase = (b * kNChunk) * kQ + qi;
    float2 v = g_end[gbase + c * kQ];

#pragma unroll
    for (int k = 0; k < 6; k++) {
        const int d = 1 << k;
        sb[tid] = v;
        __syncthreads();
        if (c >= d) {
            float2 lo = sb[tid - d];
            v.x = fmaf(p00, lo.x, fmaf(p01, lo.y, v.x));
            v.y = fmaf(p10, lo.x, fmaf(p11, lo.y, v.y));
        }
        __syncthreads();
        float t   = p00 + p11;
        float bc  = p01 * p10;
        float n00 = fmaf(p00, p00, bc);
        float n01 = p01 * t;
        float n10 = p10 * t;
        float n11 = fmaf(p11, p11, bc);
        p00 = n00; p01 = n01; p10 = n10; p11 = n11;
    }

    sb[tid] = v;
    __syncthreads();
    float2 init = (c == 0) ? make_float2(0.0f, 0.0f) : sb[tid - 1];
    g_init[gbase + c * kQ] = init;
}

// ---------------------------------------------------------------------------
// Scan pass C: re-scan chunks from corrected init, emit y + y16
// ---------------------------------------------------------------------------
__global__ __launch_bounds__(256) void k_scan_emit(
    const float* __restrict__ A, float* __restrict__ Yout)
{
    int idx = blockIdx.x * blockDim.x + threadIdx.x;
    int qi = idx & (kQ - 1);
    int c  = (idx >> 8) & (kNChunk - 1);
    int b  = idx >> 14;

    float av  = A[qi];
    float s   = 1.0f / (1.0f + kDT * kDT * av);
    float dts = kDT * s;
    float dsa = dts * av;

    size_t off = ((size_t)(b * kN + c * kCLen)) * kQ + qi;
    const __half* p = g_Bu16 + off;
    float* yp = Yout + off;
    __half* y16p = g_y16 + off;

    float2 st = g_init[idx];
    float x = st.x, z = st.y;
#pragma unroll 4
    for (int n = 0; n < kCLen; n++) {
        float bu = __half2float(p[(size_t)n * kQ]);
        float fx = dts * bu;
        float xn = fmaf(s, x, fmaf(-dsa, z, fx));
        float zn = fmaf(dts, x, fmaf(s, z, kDT * fx));
        x = xn; z = zn;
        yp[(size_t)n * kQ] = z;
        y16p[(size_t)n * kQ] = __float2half(z);
    }
}

// ---------------------------------------------------------------------------
// Launch
// ---------------------------------------------------------------------------
extern "C" void kernel_launch(void* const* d_in, const int* in_sizes, int n_in,
                              void* d_out, int out_size)
{
    const float* u  = (const float*)d_in[0];
    const float* a  = (const float*)d_in[1];
    const float* WB = (const float*)d_in[2];
    const float* bB = (const float*)d_in[3];
    const float* WC = (const float*)d_in[4];
    const float* bC = (const float*)d_in[5];
    const float* WD = (const float*)d_in[6];
    const float* bD = (const float*)d_in[7];

    float* out  = (float*)d_out;
    float* yout = out + (size_t)out_size / 2;

    static bool attr_done = false;
    if (!attr_done) {
        cudaFuncSetAttribute(k_mm_bu,  cudaFuncAttributeMaxDynamicSharedMemorySize, SMEM_BYTES);
        cudaFuncSetAttribute(k_mm_out, cudaFuncAttributeMaxDynamicSharedMemorySize, SMEM_BYTES);
        attr_done = true;
    }

    const int cvtTotal = kM * kQ / 4 + 3 * kQ * kQ / 4;
    k_cvt<<<cvtTotal / 256, 256>>>(u, WB, WC, WD);

    k_mm_bu<<<kM / TM, 256, SMEM_BYTES>>>(bB);     // 1024 blocks

    int scanThreads = kB * kNChunk * kQ;           // 262144
    k_scan_ends<<<scanThreads / 256, 256>>>(a);
    k_scan_combine<<<(kB * kQ * kNChunk) / 256, 256>>>(a);   // 1024 blocks
    k_scan_emit<<<scanThreads / 256, 256>>>(a, yout);

    k_mm_out<<<kM / TM, 256, SMEM_BYTES>>>(bC, bD, out);     // 1024 blocks
}

// round 12
// speedup vs baseline: 1.0427x; 1.0427x over previous
#include <cuda_runtime.h>
#include <cuda_fp16.h>
#include <math.h>
#include <stdint.h>

// ---------------------------------------------------------------------------
// LinOSS layer: B=16, N=4096, q=256 on sm_103
// fp16 operands pre-converted once; GEMMs: cp.async 3-stage (BK=32) HMMA.
//   u16 = fp16(u); W*16 = fp16(W*)
//   Bu16 = fp16(u16 @ WB16^T + bB); GEMM1 epilogue ALSO computes per-chunk
//          scan end-states (pass A fused; CTA tile = exactly 2 chunks)
//   y    = KS combine + emit (y fp32 + y16)
//   h    = y16@WC16^T + u16@WD16^T + bC + bD; g=gelu(h); out=g*sigmoid(g)+u16
// Output: [out | y]
// ---------------------------------------------------------------------------

namespace {
constexpr int kB = 16;
constexpr int kN = 4096;
constexpr int kQ = 256;
constexpr int kM = kB * kN;                 // 65536
constexpr float kDT = 1.0f / 4096.0f;
constexpr int kNChunk = 64;
constexpr int kCLen = kN / kNChunk;         // 64

constexpr int TM = 128, TN = 128, BK = 32;  // CTA tile, K-chunk (fp16)
constexpr int SSTR = 40;                    // smem row stride in halves (80 B)
constexpr int PL_ELEMS = TM * SSTR;         // 5120
constexpr int PL_BYTES = PL_ELEMS * 2;      // 10240
constexpr int STAGE_BYTES = 2 * PL_BYTES;   // 20480 (A plane + B plane)
constexpr int NSTAGE = 3;
constexpr int SMEM_BYTES = NSTAGE * STAGE_BYTES;  // 61440

constexpr int TSTR = 132;                   // epilogue tile stride (halves)
// epilogue tile: 128 * 132 * 2 = 33792 bytes <= SMEM_BYTES (reuses stages)
}  // namespace

// Device scratch (static; no cudaMalloc allowed)
__device__ __half g_Bu16[(size_t)kM * kQ];
__device__ float2 g_end[kB * kNChunk * kQ];
__device__ float2 g_init[kB * kNChunk * kQ];
__device__ __half g_u16[(size_t)kM * kQ];
__device__ __half g_y16[(size_t)kM * kQ];
__device__ __half g_WB16[kQ * kQ];
__device__ __half g_WC16[kQ * kQ];
__device__ __half g_WD16[kQ * kQ];

// ---------------------------------------------------------------------------
// helpers
// ---------------------------------------------------------------------------
__device__ __forceinline__ uint32_t smem_u32(const void* p) {
    uint32_t a;
    asm("{ .reg .u64 t; cvta.to.shared.u64 t, %1; cvt.u32.u64 %0, t; }" : "=r"(a) : "l"(p));
    return a;
}
__device__ __forceinline__ uint32_t packh(float a, float b) {
    __half2 h = __floats2half2_rn(a, b);
    uint32_t u; memcpy(&u, &h, 4); return u;
}
__device__ __forceinline__ void ldsm4(uint32_t (&r)[4], uint32_t addr) {
    asm volatile("ldmatrix.sync.aligned.m8n8.x4.shared.b16 {%0,%1,%2,%3}, [%4];"
                 : "=r"(r[0]), "=r"(r[1]), "=r"(r[2]), "=r"(r[3]) : "r"(addr));
}
__device__ __forceinline__ void mma16816(float* c, const uint32_t* a, const uint32_t* b) {
    asm volatile(
        "mma.sync.aligned.m16n8k16.row.col.f32.f16.f16.f32 "
        "{%0,%1,%2,%3}, {%4,%5,%6,%7}, {%8,%9}, {%0,%1,%2,%3};"
        : "+f"(c[0]), "+f"(c[1]), "+f"(c[2]), "+f"(c[3])
        : "r"(a[0]), "r"(a[1]), "r"(a[2]), "r"(a[3]), "r"(b[0]), "r"(b[1]));
}
#define CP_COMMIT() asm volatile("cp.async.commit_group;" ::: "memory")
#define CP_WAIT1()  asm volatile("cp.async.wait_group 1;" ::: "memory")

// Issue one stage: A tile (128 x 32 fp16) + B tile (128 x 32 fp16).
__device__ __forceinline__ void cpa_stage(uint32_t sb, const __half* __restrict__ aSrc,
                                          const __half* __restrict__ bSrc, int tid) {
#pragma unroll
    for (int k = 0; k < 2; k++) {
        int t = tid + k * 256;             // 0..511
        int r = t >> 2, j = t & 3;
        const __half* g = aSrc + (size_t)r * kQ + j * 8;
        uint32_t s = sb + (uint32_t)(r * 80 + j * 16);
        asm volatile("cp.async.ca.shared.global [%0], [%1], 16;" :: "r"(s), "l"(g));
    }
#pragma unroll
    for (int k = 0; k < 2; k++) {
        int t = tid + k * 256;
        int r = t >> 2, j = t & 3;
        const __half* g = bSrc + (size_t)r * kQ + j * 8;
        uint32_t s = sb + PL_BYTES + (uint32_t)(r * 80 + j * 16);
        asm volatile("cp.async.ca.shared.global [%0], [%1], 16;" :: "r"(s), "l"(g));
    }
}

// MMA over one resident stage: warp tile 32(M) x 64(N).
__device__ __forceinline__ void mma_stage(uint32_t sb, float (&acc)[2][8][4],
                                          int lane, int wm, int wn) {
    const int g = lane >> 3, l = lane & 7;
#pragma unroll
    for (int k16 = 0; k16 < 2; k16++) {
        uint32_t afrag[2][4];
        const int acol = k16 * 16 + (g >> 1) * 8;
#pragma unroll
        for (int mt = 0; mt < 2; mt++) {
            const int arow = wm + mt * 16 + (g & 1) * 8 + l;
            ldsm4(afrag[mt], sb + (uint32_t)(arow * SSTR + acol) * 2);
        }
        const int bcol = k16 * 16 + (g & 1) * 8;
#pragma unroll
        for (int np = 0; np < 4; np++) {
            const int brow = wn + np * 16 + (g >> 1) * 8 + l;
            uint32_t bfrag[4];
            ldsm4(bfrag, sb + PL_BYTES + (uint32_t)(brow * SSTR + bcol) * 2);
#pragma unroll
            for (int mt = 0; mt < 2; mt++) {
#pragma unroll
                for (int nt = 0; nt < 2; nt++) {
                    mma16816(acc[mt][np * 2 + nt], afrag[mt], &bfrag[nt * 2]);
                }
            }
        }
    }
}

// ---------------------------------------------------------------------------
// Converter: u (16M elems) + WB/WC/WD (64K each), one kernel.
// ---------------------------------------------------------------------------
__global__ __launch_bounds__(256) void k_cvt(const float* __restrict__ u,
                                             const float* __restrict__ wb,
                                             const float* __restrict__ wc,
                                             const float* __restrict__ wd) {
    const int uN = kM * kQ / 4;
    const int per = kQ * kQ / 4;
    int i = blockIdx.x * blockDim.x + threadIdx.x;
    const float* s;
    __half* d;
    int j;
    if (i < uN) { s = u; d = g_u16; j = i; }
    else {
        int w = i - uN;
        s = (w < per) ? wb : (w < 2 * per ? wc : wd);
        d = (w < per) ? g_WB16 : (w < 2 * per ? g_WC16 : g_WD16);
        j = w % per;
    }
    float4 v = reinterpret_cast<const float4*>(s)[j];
    uint2 o; o.x = packh(v.x, v.y); o.y = packh(v.z, v.w);
    reinterpret_cast<uint2*>(d)[j] = o;
}

// ---------------------------------------------------------------------------
// GEMM1: g_Bu16 = fp16(u16 @ WB16^T + bias), fused scan pass A.
// grid = (2, 512); CTA covers 128 rows = exactly 2 chunks of 64.
// ---------------------------------------------------------------------------
__global__ __launch_bounds__(256, 2) void k_mm_bu(const float* __restrict__ bias,
                                                  const float* __restrict__ A)
{
    extern __shared__ __half smem[];
    const int tid = threadIdx.x;
    const int bn = blockIdx.x, bm = blockIdx.y;
    const int tileRow = bm * TM;
    const int cb = bn * TN;
    const int lane = tid & 31, wid = tid >> 5;
    const int wm = (wid & 3) * 32, wn = (wid >> 2) * 64;
    const uint32_t smb = smem_u32(smem);

    float acc[2][8][4];
#pragma unroll
    for (int a = 0; a < 2; a++)
#pragma unroll
        for (int b = 0; b < 8; b++)
#pragma unroll
            for (int c = 0; c < 4; c++) acc[a][b][c] = 0.0f;

    const __half* aBase = g_u16 + (size_t)tileRow * kQ;
    const __half* bBase = g_WB16 + (size_t)cb * kQ;

    cpa_stage(smb, aBase, bBase, tid); CP_COMMIT();
    cpa_stage(smb + STAGE_BYTES, aBase + BK, bBase + BK, tid); CP_COMMIT();

    constexpr int C = kQ / BK;     // 8
    for (int c = 0; c < C; c++) {
        CP_WAIT1();
        __syncthreads();
        if (c + 2 < C)
            cpa_stage(smb + ((c + 2) % NSTAGE) * STAGE_BYTES,
                      aBase + (c + 2) * BK, bBase + (c + 2) * BK, tid);
        CP_COMMIT();
        mma_stage(smb + (c % NSTAGE) * STAGE_BYTES, acc, lane, wm, wn);
    }

    // all warps done with stage smem before we overwrite it with the tile
    __syncthreads();

    const int r0 = tileRow + wm + (lane >> 2);
#pragma unroll
    for (int mt = 0; mt < 2; mt++) {
        const int rr = r0 + mt * 16;
#pragma unroll
        for (int nt = 0; nt < 8; nt++) {
            const int lc = wn + nt * 8 + (lane & 3) * 2;   // local col 0..127
            const int cc = cb + lc;
            const float b0 = bias[cc], b1 = bias[cc + 1];
            uint32_t lo = packh(acc[mt][nt][0] + b0, acc[mt][nt][1] + b1);
            uint32_t hi = packh(acc[mt][nt][2] + b0, acc[mt][nt][3] + b1);
            *reinterpret_cast<uint32_t*>(&g_Bu16[(size_t)rr * kQ + cc]) = lo;
            *reinterpret_cast<uint32_t*>(&g_Bu16[(size_t)(rr + 8) * kQ + cc]) = hi;
            const int lr0 = rr - tileRow;                  // local row
            *reinterpret_cast<uint32_t*>(&smem[lr0 * TSTR + lc]) = lo;
            *reinterpret_cast<uint32_t*>(&smem[(lr0 + 8) * TSTR + lc]) = hi;
        }
    }
    __syncthreads();

    // fused scan pass A: 256 threads, one per (chunkLocal, col)
    {
        const int col = tid & (TN - 1);                    // 0..127
        const int chunkLocal = tid >> 7;                   // 0 or 1
        const int qi = cb + col;

        float av  = A[qi];
        float s   = 1.0f / (1.0f + kDT * kDT * av);
        float dts = kDT * s;
        float dsa = dts * av;

        const __half* t = smem + (chunkLocal * kCLen) * TSTR + col;
        float x = 0.0f, z = 0.0f;
#pragma unroll 4
        for (int n = 0; n < kCLen; n++) {
            float bu = __half2float(t[n * TSTR]);
            float fx = dts * bu;
            float xn = fmaf(s, x, fmaf(-dsa, z, fx));
            float zn = fmaf(dts, x, fmaf(s, z, kDT * fx));
            x = xn; z = zn;
        }
        const int b = tileRow >> 12;                        // / kN
        const int chunk = ((tileRow >> 6) & (kNChunk - 1)) + chunkLocal;
        g_end[(b * kNChunk + chunk) * kQ + qi] = make_float2(x, z);
    }
}

// ---------------------------------------------------------------------------
// GEMM2: h = y16@WC16^T + u16@WD16^T + bC + bD; gelu+glu epilogue,
// residual from u16.
// ---------------------------------------------------------------------------
__global__ __launch_bounds__(256, 2) void k_mm_out(
    const float* __restrict__ bC, const float* __restrict__ bD,
    float* __restrict__ Out)
{
    extern __shared__ __half smem[];
    const int tid = threadIdx.x;
    const int bn = blockIdx.x, bm = blockIdx.y;
    const int tileRow = bm * TM;
    const int lane = tid & 31, wid = tid >> 5;
    const int wm = (wid & 3) * 32, wn = (wid >> 2) * 64;
    const uint32_t smb = smem_u32(smem);

    float acc[2][8][4];
#pragma unroll
    for (int a = 0; a < 2; a++)
#pragma unroll
        for (int b = 0; b < 8; b++)
#pragma unroll
            for (int c = 0; c < 4; c++) acc[a][b][c] = 0.0f;

    constexpr int C = 2 * kQ / BK;   // 16
    auto aPtr = [&](int n) -> const __half* {
        return (n < C / 2 ? g_y16 : g_u16) + (size_t)tileRow * kQ + (n & (C / 2 - 1)) * BK;
    };
    auto bPtr = [&](int n) -> const __half* {
        return (n < C / 2 ? g_WC16 : g_WD16) + (size_t)bn * TN * kQ + (n & (C / 2 - 1)) * BK;
    };

    cpa_stage(smb, aPtr(0), bPtr(0), tid); CP_COMMIT();
    cpa_stage(smb + STAGE_BYTES, aPtr(1), bPtr(1), tid); CP_COMMIT();

    for (int c = 0; c < C; c++) {
        CP_WAIT1();
        __syncthreads();
        if (c + 2 < C)
            cpa_stage(smb + ((c + 2) % NSTAGE) * STAGE_BYTES, aPtr(c + 2), bPtr(c + 2), tid);
        CP_COMMIT();
        mma_stage(smb + (c % NSTAGE) * STAGE_BYTES, acc, lane, wm, wn);
    }

    const int r0 = tileRow + wm + (lane >> 2);
    const int cbase = bn * TN + wn;
#pragma unroll
    for (int mt = 0; mt < 2; mt++) {
        const int rr = r0 + mt * 16;
#pragma unroll
        for (int nt = 0; nt < 8; nt++) {
            const int cc = cbase + nt * 8 + (lane & 3) * 2;
            const float b0 = bC[cc] + bD[cc], b1 = bC[cc + 1] + bD[cc + 1];
#pragma unroll
            for (int half = 0; half < 2; half++) {
                const int row = rr + half * 8;
                float h0 = acc[mt][nt][half * 2 + 0] + b0;
                float h1 = acc[mt][nt][half * 2 + 1] + b1;
                __half2 uh = *reinterpret_cast<const __half2*>(&g_u16[(size_t)row * kQ + cc]);
                float2 uv = __half22float2(uh);
                float g0 = 0.5f * h0 * (1.0f + erff(h0 * 0.70710678118654752f));
                float g1 = 0.5f * h1 * (1.0f + erff(h1 * 0.70710678118654752f));
                float o0 = fmaf(g0, 1.0f / (1.0f + __expf(-g0)), uv.x);
                float o1 = fmaf(g1, 1.0f / (1.0f + __expf(-g1)), uv.y);
                float2 w; w.x = o0; w.y = o1;
                *reinterpret_cast<float2*>(&Out[(size_t)row * kQ + cc]) = w;
            }
        }
    }
}

// ---------------------------------------------------------------------------
// Scan pass B: PARALLEL chunk-prefix combine (Kogge-Stone affine scan).
// Per-chunk linear part P_chunk = M^kCLen (pre-squared 6x from M).
// ---------------------------------------------------------------------------
__global__ __launch_bounds__(256) void k_scan_combine(const float* __restrict__ A)
{
    __shared__ float2 sb[256];
    const int tid = threadIdx.x;
    const int c = tid & (kNChunk - 1);                 // chunk 0..63
    const int pairIdx = blockIdx.x * 4 + (tid >> 6);   // (b,qi) pair
    const int qi = pairIdx & (kQ - 1);
    const int b  = pairIdx >> 8;

    float av  = A[qi];
    float s   = 1.0f / (1.0f + kDT * kDT * av);
    float dts = kDT * s;
    float dsa = dts * av;

    float p00 = s, p01 = -dsa, p10 = dts, p11 = s;
#pragma unroll
    for (int k = 0; k < 6; k++) {          // M -> M^64 = P_chunk
        float t   = p00 + p11;
        float bc  = p01 * p10;
        float n00 = fmaf(p00, p00, bc);
        float n01 = p01 * t;
        float n10 = p10 * t;
        float n11 = fmaf(p11, p11, bc);
        p00 = n00; p01 = n01; p10 = n10; p11 = n11;
    }

    const int gbase = (b * kNChunk) * kQ + qi;
    float2 v = g_end[gbase + c * kQ];

#pragma unroll
    for (int k = 0; k < 6; k++) {
        const int d = 1 << k;
        sb[tid] = v;
        __syncthreads();
        if (c >= d) {
            float2 lo = sb[tid - d];
            v.x = fmaf(p00, lo.x, fmaf(p01, lo.y, v.x));
            v.y = fmaf(p10, lo.x, fmaf(p11, lo.y, v.y));
        }
        __syncthreads();
        float t   = p00 + p11;
        float bc  = p01 * p10;
        float n00 = fmaf(p00, p00, bc);
        float n01 = p01 * t;
        float n10 = p10 * t;
        float n11 = fmaf(p11, p11, bc);
        p00 = n00; p01 = n01; p10 = n10; p11 = n11;
    }

    sb[tid] = v;
    __syncthreads();
    float2 init = (c == 0) ? make_float2(0.0f, 0.0f) : sb[tid - 1];
    g_init[gbase + c * kQ] = init;
}

// ---------------------------------------------------------------------------
// Scan pass C: re-scan chunks from corrected init, emit y + y16
// ---------------------------------------------------------------------------
__global__ __launch_bounds__(256) void k_scan_emit(
    const float* __restrict__ A, float* __restrict__ Yout)
{
    int idx = blockIdx.x * blockDim.x + threadIdx.x;
    int qi = idx & (kQ - 1);
    int c  = (idx >> 8) & (kNChunk - 1);
    int b  = idx >> 14;

    float av  = A[qi];
    float s   = 1.0f / (1.0f + kDT * kDT * av);
    float dts = kDT * s;
    float dsa = dts * av;

    size_t off = ((size_t)(b * kN + c * kCLen)) * kQ + qi;
    const __half* p = g_Bu16 + off;
    float* yp = Yout + off;
    __half* y16p = g_y16 + off;

    float2 st = g_init[idx];
    float x = st.x, z = st.y;
#pragma unroll 4
    for (int n = 0; n < kCLen; n++) {
        float bu = __half2float(p[(size_t)n * kQ]);
        float fx = dts * bu;
        float xn = fmaf(s, x, fmaf(-dsa, z, fx));
        float zn = fmaf(dts, x, fmaf(s, z, kDT * fx));
        x = xn; z = zn;
        yp[(size_t)n * kQ] = z;
        y16p[(size_t)n * kQ] = __float2half(z);
    }
}

// ---------------------------------------------------------------------------
// Launch
// ---------------------------------------------------------------------------
extern "C" void kernel_launch(void* const* d_in, const int* in_sizes, int n_in,
                              void* d_out, int out_size)
{
    const float* u  = (const float*)d_in[0];
    const float* a  = (const float*)d_in[1];
    const float* WB = (const float*)d_in[2];
    const float* bB = (const float*)d_in[3];
    const float* WC = (const float*)d_in[4];
    const float* bC = (const float*)d_in[5];
    const float* WD = (const float*)d_in[6];
    const float* bD = (const float*)d_in[7];

    float* out  = (float*)d_out;
    float* yout = out + (size_t)out_size / 2;

    static bool attr_done = false;
    if (!attr_done) {
        cudaFuncSetAttribute(k_mm_bu,  cudaFuncAttributeMaxDynamicSharedMemorySize, SMEM_BYTES);
        cudaFuncSetAttribute(k_mm_out, cudaFuncAttributeMaxDynamicSharedMemorySize, SMEM_BYTES);
        attr_done = true;
    }

    const int cvtTotal = kM * kQ / 4 + 3 * kQ * kQ / 4;
    k_cvt<<<cvtTotal / 256, 256>>>(u, WB, WC, WD);

    dim3 grid(kQ / TN, kM / TM);                // (2, 512)
    k_mm_bu<<<grid, 256, SMEM_BYTES>>>(bB, a);  // fused pass A

    k_scan_combine<<<(kB * kQ * kNChunk) / 256, 256>>>(a);   // 1024 blocks
    int scanThreads = kB * kNChunk * kQ;        // 262144
    k_scan_emit<<<scanThreads / 256, 256>>>(a, yout);

    k_mm_out<<<grid, 256, SMEM_BYTES>>>(bC, bD, out);
}

// round 13
// speedup vs baseline: 1.0540x; 1.0109x over previous
#include <cuda_runtime.h>
#include <cuda_fp16.h>
#include <math.h>
#include <stdint.h>

// ---------------------------------------------------------------------------
// LinOSS layer: B=16, N=4096, q=256 on sm_103
// fp16 operands pre-converted once; GEMMs: cp.async 3-stage (BK=32) HMMA.
//   u16 = fp16(u); W*16 = fp16(W*)
//   Bu16 = fp16(u16 @ WB16^T + bB)
//   y    = IM scan over Bu16 (chunked 3-pass, KS combine); y fp32 + y16
//          (ends/emit process 2 channels per thread via __half2)
//   h    = y16@WC16^T + u16@WD16^T + bC + bD; g=gelu(h); out=g*sigmoid(g)+u16
// Output: [out | y]
// ---------------------------------------------------------------------------

namespace {
constexpr int kB = 16;
constexpr int kN = 4096;
constexpr int kQ = 256;
constexpr int kM = kB * kN;                 // 65536
constexpr float kDT = 1.0f / 4096.0f;
constexpr int kNChunk = 64;
constexpr int kCLen = kN / kNChunk;         // 64

constexpr int TM = 128, TN = 128, BK = 32;  // CTA tile, K-chunk (fp16)
constexpr int SSTR = 40;                    // smem row stride in halves (80 B)
constexpr int PL_ELEMS = TM * SSTR;         // 5120
constexpr int PL_BYTES = PL_ELEMS * 2;      // 10240
constexpr int STAGE_BYTES = 2 * PL_BYTES;   // 20480 (A plane + B plane)
constexpr int NSTAGE = 3;
constexpr int SMEM_BYTES = NSTAGE * STAGE_BYTES;  // 61440
}  // namespace

// Device scratch (static; no cudaMalloc allowed)
__device__ __half g_Bu16[(size_t)kM * kQ];
__device__ float2 g_end[kB * kNChunk * kQ];
__device__ float2 g_init[kB * kNChunk * kQ];
__device__ __half g_u16[(size_t)kM * kQ];
__device__ __half g_y16[(size_t)kM * kQ];
__device__ __half g_WB16[kQ * kQ];
__device__ __half g_WC16[kQ * kQ];
__device__ __half g_WD16[kQ * kQ];

// ---------------------------------------------------------------------------
// helpers
// ---------------------------------------------------------------------------
__device__ __forceinline__ uint32_t smem_u32(const void* p) {
    uint32_t a;
    asm("{ .reg .u64 t; cvta.to.shared.u64 t, %1; cvt.u32.u64 %0, t; }" : "=r"(a) : "l"(p));
    return a;
}
__device__ __forceinline__ uint32_t packh(float a, float b) {
    __half2 h = __floats2half2_rn(a, b);
    uint32_t u; memcpy(&u, &h, 4); return u;
}
__device__ __forceinline__ void ldsm4(uint32_t (&r)[4], uint32_t addr) {
    asm volatile("ldmatrix.sync.aligned.m8n8.x4.shared.b16 {%0,%1,%2,%3}, [%4];"
                 : "=r"(r[0]), "=r"(r[1]), "=r"(r[2]), "=r"(r[3]) : "r"(addr));
}
__device__ __forceinline__ void mma16816(float* c, const uint32_t* a, const uint32_t* b) {
    asm volatile(
        "mma.sync.aligned.m16n8k16.row.col.f32.f16.f16.f32 "
        "{%0,%1,%2,%3}, {%4,%5,%6,%7}, {%8,%9}, {%0,%1,%2,%3};"
        : "+f"(c[0]), "+f"(c[1]), "+f"(c[2]), "+f"(c[3])
        : "r"(a[0]), "r"(a[1]), "r"(a[2]), "r"(a[3]), "r"(b[0]), "r"(b[1]));
}
#define CP_COMMIT() asm volatile("cp.async.commit_group;" ::: "memory")
#define CP_WAIT1()  asm volatile("cp.async.wait_group 1;" ::: "memory")

// Issue one stage: A tile (128 x 32 fp16) + B tile (128 x 32 fp16).
__device__ __forceinline__ void cpa_stage(uint32_t sb, const __half* __restrict__ aSrc,
                                          const __half* __restrict__ bSrc, int tid) {
#pragma unroll
    for (int k = 0; k < 2; k++) {
        int t = tid + k * 256;             // 0..511
        int r = t >> 2, j = t & 3;
        const __half* g = aSrc + (size_t)r * kQ + j * 8;
        uint32_t s = sb + (uint32_t)(r * 80 + j * 16);
        asm volatile("cp.async.ca.shared.global [%0], [%1], 16;" :: "r"(s), "l"(g));
    }
#pragma unroll
    for (int k = 0; k < 2; k++) {
        int t = tid + k * 256;
        int r = t >> 2, j = t & 3;
        const __half* g = bSrc + (size_t)r * kQ + j * 8;
        uint32_t s = sb + PL_BYTES + (uint32_t)(r * 80 + j * 16);
        asm volatile("cp.async.ca.shared.global [%0], [%1], 16;" :: "r"(s), "l"(g));
    }
}

// MMA over one resident stage: warp tile 32(M) x 64(N).
__device__ __forceinline__ void mma_stage(uint32_t sb, float (&acc)[2][8][4],
                                          int lane, int wm, int wn) {
    const int g = lane >> 3, l = lane & 7;
#pragma unroll
    for (int k16 = 0; k16 < 2; k16++) {
        uint32_t afrag[2][4];
        const int acol = k16 * 16 + (g >> 1) * 8;
#pragma unroll
        for (int mt = 0; mt < 2; mt++) {
            const int arow = wm + mt * 16 + (g & 1) * 8 + l;
            ldsm4(afrag[mt], sb + (uint32_t)(arow * SSTR + acol) * 2);
        }
        const int bcol = k16 * 16 + (g & 1) * 8;
#pragma unroll
        for (int np = 0; np < 4; np++) {
            const int brow = wn + np * 16 + (g >> 1) * 8 + l;
            uint32_t bfrag[4];
            ldsm4(bfrag, sb + PL_BYTES + (uint32_t)(brow * SSTR + bcol) * 2);
#pragma unroll
            for (int mt = 0; mt < 2; mt++) {
#pragma unroll
                for (int nt = 0; nt < 2; nt++) {
                    mma16816(acc[mt][np * 2 + nt], afrag[mt], &bfrag[nt * 2]);
                }
            }
        }
    }
}

// ---------------------------------------------------------------------------
// Converter: u (16M elems) + WB/WC/WD (64K each), one kernel.
// ---------------------------------------------------------------------------
__global__ __launch_bounds__(256) void k_cvt(const float* __restrict__ u,
                                             const float* __restrict__ wb,
                                             const float* __restrict__ wc,
                                             const float* __restrict__ wd) {
    const int uN = kM * kQ / 4;
    const int per = kQ * kQ / 4;
    int i = blockIdx.x * blockDim.x + threadIdx.x;
    const float* s;
    __half* d;
    int j;
    if (i < uN) { s = u; d = g_u16; j = i; }
    else {
        int w = i - uN;
        s = (w < per) ? wb : (w < 2 * per ? wc : wd);
        d = (w < per) ? g_WB16 : (w < 2 * per ? g_WC16 : g_WD16);
        j = w % per;
    }
    float4 v = reinterpret_cast<const float4*>(s)[j];
    uint2 o; o.x = packh(v.x, v.y); o.y = packh(v.z, v.w);
    reinterpret_cast<uint2*>(d)[j] = o;
}

// ---------------------------------------------------------------------------
// GEMM1: g_Bu16 = fp16(u16 @ WB16^T + bias)
// ---------------------------------------------------------------------------
__global__ __launch_bounds__(256, 2) void k_mm_bu(const float* __restrict__ bias)
{
    extern __shared__ __half smem[];
    const int tid = threadIdx.x;
    const int bn = blockIdx.x, bm = blockIdx.y;
    const int tileRow = bm * TM;
    const int lane = tid & 31, wid = tid >> 5;
    const int wm = (wid & 3) * 32, wn = (wid >> 2) * 64;
    const uint32_t smb = smem_u32(smem);

    float acc[2][8][4];
#pragma unroll
    for (int a = 0; a < 2; a++)
#pragma unroll
        for (int b = 0; b < 8; b++)
#pragma unroll
            for (int c = 0; c < 4; c++) acc[a][b][c] = 0.0f;

    const __half* aBase = g_u16 + (size_t)tileRow * kQ;
    const __half* bBase = g_WB16 + (size_t)bn * TN * kQ;

    cpa_stage(smb, aBase, bBase, tid); CP_COMMIT();
    cpa_stage(smb + STAGE_BYTES, aBase + BK, bBase + BK, tid); CP_COMMIT();

    constexpr int C = kQ / BK;     // 8
    for (int c = 0; c < C; c++) {
        CP_WAIT1();
        __syncthreads();
        if (c + 2 < C)
            cpa_stage(smb + ((c + 2) % NSTAGE) * STAGE_BYTES,
                      aBase + (c + 2) * BK, bBase + (c + 2) * BK, tid);
        CP_COMMIT();
        mma_stage(smb + (c % NSTAGE) * STAGE_BYTES, acc, lane, wm, wn);
    }

    const int r0 = tileRow + wm + (lane >> 2);
    const int cb = bn * TN + wn;
#pragma unroll
    for (int mt = 0; mt < 2; mt++) {
        const int rr = r0 + mt * 16;
#pragma unroll
        for (int nt = 0; nt < 8; nt++) {
            const int cc = cb + nt * 8 + (lane & 3) * 2;
            const float b0 = bias[cc], b1 = bias[cc + 1];
            uint32_t lo = packh(acc[mt][nt][0] + b0, acc[mt][nt][1] + b1);
            uint32_t hi = packh(acc[mt][nt][2] + b0, acc[mt][nt][3] + b1);
            *reinterpret_cast<uint32_t*>(&g_Bu16[(size_t)rr * kQ + cc]) = lo;
            *reinterpret_cast<uint32_t*>(&g_Bu16[(size_t)(rr + 8) * kQ + cc]) = hi;
        }
    }
}

// ---------------------------------------------------------------------------
// GEMM2: h = y16@WC16^T + u16@WD16^T + bC + bD; gelu+glu epilogue,
// residual from u16.
// ---------------------------------------------------------------------------
__global__ __launch_bounds__(256, 2) void k_mm_out(
    const float* __restrict__ bC, const float* __restrict__ bD,
    float* __restrict__ Out)
{
    extern __shared__ __half smem[];
    const int tid = threadIdx.x;
    const int bn = blockIdx.x, bm = blockIdx.y;
    const int tileRow = bm * TM;
    const int lane = tid & 31, wid = tid >> 5;
    const int wm = (wid & 3) * 32, wn = (wid >> 2) * 64;
    const uint32_t smb = smem_u32(smem);

    float acc[2][8][4];
#pragma unroll
    for (int a = 0; a < 2; a++)
#pragma unroll
        for (int b = 0; b < 8; b++)
#pragma unroll
            for (int c = 0; c < 4; c++) acc[a][b][c] = 0.0f;

    constexpr int C = 2 * kQ / BK;   // 16
    auto aPtr = [&](int n) -> const __half* {
        return (n < C / 2 ? g_y16 : g_u16) + (size_t)tileRow * kQ + (n & (C / 2 - 1)) * BK;
    };
    auto bPtr = [&](int n) -> const __half* {
        return (n < C / 2 ? g_WC16 : g_WD16) + (size_t)bn * TN * kQ + (n & (C / 2 - 1)) * BK;
    };

    cpa_stage(smb, aPtr(0), bPtr(0), tid); CP_COMMIT();
    cpa_stage(smb + STAGE_BYTES, aPtr(1), bPtr(1), tid); CP_COMMIT();

    for (int c = 0; c < C; c++) {
        CP_WAIT1();
        __syncthreads();
        if (c + 2 < C)
            cpa_stage(smb + ((c + 2) % NSTAGE) * STAGE_BYTES, aPtr(c + 2), bPtr(c + 2), tid);
        CP_COMMIT();
        mma_stage(smb + (c % NSTAGE) * STAGE_BYTES, acc, lane, wm, wn);
    }

    const int r0 = tileRow + wm + (lane >> 2);
    const int cbase = bn * TN + wn;
#pragma unroll
    for (int mt = 0; mt < 2; mt++) {
        const int rr = r0 + mt * 16;
#pragma unroll
        for (int nt = 0; nt < 8; nt++) {
            const int cc = cbase + nt * 8 + (lane & 3) * 2;
            const float b0 = bC[cc] + bD[cc], b1 = bC[cc + 1] + bD[cc + 1];
#pragma unroll
            for (int half = 0; half < 2; half++) {
                const int row = rr + half * 8;
                float h0 = acc[mt][nt][half * 2 + 0] + b0;
                float h1 = acc[mt][nt][half * 2 + 1] + b1;
                __half2 uh = *reinterpret_cast<const __half2*>(&g_u16[(size_t)row * kQ + cc]);
                float2 uv = __half22float2(uh);
                float g0 = 0.5f * h0 * (1.0f + erff(h0 * 0.70710678118654752f));
                float g1 = 0.5f * h1 * (1.0f + erff(h1 * 0.70710678118654752f));
                float o0 = fmaf(g0, 1.0f / (1.0f + __expf(-g0)), uv.x);
                float o1 = fmaf(g1, 1.0f / (1.0f + __expf(-g1)), uv.y);
                float2 w; w.x = o0; w.y = o1;
                *reinterpret_cast<float2*>(&Out[(size_t)row * kQ + cc]) = w;
            }
        }
    }
}

// ---------------------------------------------------------------------------
// Scan pass A: per-chunk end states — 2 channels per thread (__half2 loads)
// ---------------------------------------------------------------------------
__global__ __launch_bounds__(256) void k_scan_ends(const float* __restrict__ A)
{
    int idx = blockIdx.x * blockDim.x + threadIdx.x;   // < kB*kNChunk*kQ/2
    int q2 = idx & (kQ / 2 - 1);                       // column pair 0..127
    int c  = (idx >> 7) & (kNChunk - 1);
    int b  = idx >> 13;
    int qi = q2 * 2;

    float2 av = *reinterpret_cast<const float2*>(&A[qi]);
    float s0   = 1.0f / (1.0f + kDT * kDT * av.x);
    float dts0 = kDT * s0, dsa0 = dts0 * av.x;
    float s1   = 1.0f / (1.0f + kDT * kDT * av.y);
    float dts1 = kDT * s1, dsa1 = dts1 * av.y;

    const __half2* p = reinterpret_cast<const __half2*>(
        g_Bu16 + ((size_t)(b * kN + c * kCLen)) * kQ + qi);
    float x0 = 0.0f, z0 = 0.0f, x1 = 0.0f, z1 = 0.0f;
#pragma unroll 8
    for (int n = 0; n < kCLen; n++) {
        float2 bu = __half22float2(p[(size_t)n * (kQ / 2)]);
        float fx0 = dts0 * bu.x;
        float xn0 = fmaf(s0, x0, fmaf(-dsa0, z0, fx0));
        float zn0 = fmaf(dts0, x0, fmaf(s0, z0, kDT * fx0));
        x0 = xn0; z0 = zn0;
        float fx1 = dts1 * bu.y;
        float xn1 = fmaf(s1, x1, fmaf(-dsa1, z1, fx1));
        float zn1 = fmaf(dts1, x1, fmaf(s1, z1, kDT * fx1));
        x1 = xn1; z1 = zn1;
    }
    float4 o; o.x = x0; o.y = z0; o.z = x1; o.w = z1;
    *reinterpret_cast<float4*>(&g_end[(b * kNChunk + c) * kQ + qi]) = o;
}

// ---------------------------------------------------------------------------
// Scan pass B: PARALLEL chunk-prefix combine (Kogge-Stone affine scan).
// Per-chunk linear part P_chunk = M^kCLen (pre-squared 6x from M).
// ---------------------------------------------------------------------------
__global__ __launch_bounds__(256) void k_scan_combine(const float* __restrict__ A)
{
    __shared__ float2 sb[256];
    const int tid = threadIdx.x;
    const int c = tid & (kNChunk - 1);                 // chunk 0..63
    const int pairIdx = blockIdx.x * 4 + (tid >> 6);   // (b,qi) pair
    const int qi = pairIdx & (kQ - 1);
    const int b  = pairIdx >> 8;

    float av  = A[qi];
    float s   = 1.0f / (1.0f + kDT * kDT * av);
    float dts = kDT * s;
    float dsa = dts * av;

    float p00 = s, p01 = -dsa, p10 = dts, p11 = s;
#pragma unroll
    for (int k = 0; k < 6; k++) {          // M -> M^64 = P_chunk
        float t   = p00 + p11;
        float bc  = p01 * p10;
        float n00 = fmaf(p00, p00, bc);
        float n01 = p01 * t;
        float n10 = p10 * t;
        float n11 = fmaf(p11, p11, bc);
        p00 = n00; p01 = n01; p10 = n10; p11 = n11;
    }

    const int gbase = (b * kNChunk) * kQ + qi;
    float2 v = g_end[gbase + c * kQ];

#pragma unroll
    for (int k = 0; k < 6; k++) {
        const int d = 1 << k;
        sb[tid] = v;
        __syncthreads();
        if (c >= d) {
            float2 lo = sb[tid - d];
            v.x = fmaf(p00, lo.x, fmaf(p01, lo.y, v.x));
            v.y = fmaf(p10, lo.x, fmaf(p11, lo.y, v.y));
        }
        __syncthreads();
        float t   = p00 + p11;
        float bc  = p01 * p10;
        float n00 = fmaf(p00, p00, bc);
        float n01 = p01 * t;
        float n10 = p10 * t;
        float n11 = fmaf(p11, p11, bc);
        p00 = n00; p01 = n01; p10 = n10; p11 = n11;
    }

    sb[tid] = v;
    __syncthreads();
    float2 init = (c == 0) ? make_float2(0.0f, 0.0f) : sb[tid - 1];
    g_init[gbase + c * kQ] = init;
}

// ---------------------------------------------------------------------------
// Scan pass C: re-scan chunks, emit y + y16 — 2 channels per thread
// ---------------------------------------------------------------------------
__global__ __launch_bounds__(256) void k_scan_emit(
    const float* __restrict__ A, float* __restrict__ Yout)
{
    int idx = blockIdx.x * blockDim.x + threadIdx.x;   // < kB*kNChunk*kQ/2
    int q2 = idx & (kQ / 2 - 1);
    int c  = (idx >> 7) & (kNChunk - 1);
    int b  = idx >> 13;
    int qi = q2 * 2;

    float2 av = *reinterpret_cast<const float2*>(&A[qi]);
    float s0   = 1.0f / (1.0f + kDT * kDT * av.x);
    float dts0 = kDT * s0, dsa0 = dts0 * av.x;
    float s1   = 1.0f / (1.0f + kDT * kDT * av.y);
    float dts1 = kDT * s1, dsa1 = dts1 * av.y;

    size_t off = ((size_t)(b * kN + c * kCLen)) * kQ + qi;
    const __half2* p = reinterpret_cast<const __half2*>(g_Bu16 + off);
    float* yp = Yout + off;
    __half2* y16p = reinterpret_cast<__half2*>(g_y16 + off);

    float4 st = *reinterpret_cast<const float4*>(&g_init[(b * kNChunk + c) * kQ + qi]);
    float x0 = st.x, z0 = st.y, x1 = st.z, z1 = st.w;
#pragma unroll 8
    for (int n = 0; n < kCLen; n++) {
        float2 bu = __half22float2(p[(size_t)n * (kQ / 2)]);
        float fx0 = dts0 * bu.x;
        float xn0 = fmaf(s0, x0, fmaf(-dsa0, z0, fx0));
        float zn0 = fmaf(dts0, x0, fmaf(s0, z0, kDT * fx0));
        x0 = xn0; z0 = zn0;
        float fx1 = dts1 * bu.y;
        float xn1 = fmaf(s1, x1, fmaf(-dsa1, z1, fx1));
        float zn1 = fmaf(dts1, x1, fmaf(s1, z1, kDT * fx1));
        x1 = xn1; z1 = zn1;
        float2 yo; yo.x = z0; yo.y = z1;
        *reinterpret_cast<float2*>(yp + (size_t)n * kQ) = yo;
        y16p[(size_t)n * (kQ / 2)] = __floats2half2_rn(z0, z1);
    }
}

// ---------------------------------------------------------------------------
// Launch
// ---------------------------------------------------------------------------
extern "C" void kernel_launch(void* const* d_in, const int* in_sizes, int n_in,
                              void* d_out, int out_size)
{
    const float* u  = (const float*)d_in[0];
    const float* a  = (const float*)d_in[1];
    const float* WB = (const float*)d_in[2];
    const float* bB = (const float*)d_in[3];
    const float* WC = (const float*)d_in[4];
    const float* bC = (const float*)d_in[5];
    const float* WD = (const float*)d_in[6];
    const float* bD = (const float*)d_in[7];

    float* out  = (float*)d_out;
    float* yout = out + (size_t)out_size / 2;

    static bool attr_done = false;
    if (!attr_done) {
        cudaFuncSetAttribute(k_mm_bu,  cudaFuncAttributeMaxDynamicSharedMemorySize, SMEM_BYTES);
        cudaFuncSetAttribute(k_mm_out, cudaFuncAttributeMaxDynamicSharedMemorySize, SMEM_BYTES);
        attr_done = true;
    }

    const int cvtTotal = kM * kQ / 4 + 3 * kQ * kQ / 4;
    k_cvt<<<cvtTotal / 256, 256>>>(u, WB, WC, WD);

    dim3 grid(kQ / TN, kM / TM);                // (2, 512)
    k_mm_bu<<<grid, 256, SMEM_BYTES>>>(bB);

    int scanPairs = kB * kNChunk * kQ / 2;      // 131072
    k_scan_ends<<<scanPairs / 256, 256>>>(a);
    k_scan_combine<<<(kB * kQ * kNChunk) / 256, 256>>>(a);   // 1024 blocks
    k_scan_emit<<<scanPairs / 256, 256>>>(a, yout);

    k_mm_out<<<grid, 256, SMEM_BYTES>>>(bC, bD, out);
}

// round 14
// speedup vs baseline: 1.0895x; 1.0337x over previous
#include <cuda_runtime.h>
#include <cuda_fp16.h>
#include <math.h>
#include <stdint.h>

// ---------------------------------------------------------------------------
// LinOSS layer: B=16, N=4096, q=256 on sm_103
// fp16 operands pre-converted once; GEMMs: cp.async 2-stage (BK=64) HMMA.
//   u16 = fp16(u); W*16 = fp16(W*)
//   Bu16 = fp16(u16 @ WB16^T + bB)
//   y    = IM scan over Bu16 (chunked 3-pass, KS combine); y fp32 + y16
//   h    = y16@WC16^T + u16@WD16^T + bC + bD; g=gelu(h); out=g*sigmoid(g)+u16
// Output: [out | y]
// ---------------------------------------------------------------------------

namespace {
constexpr int kB = 16;
constexpr int kN = 4096;
constexpr int kQ = 256;
constexpr int kM = kB * kN;                 // 65536
constexpr float kDT = 1.0f / 4096.0f;
constexpr int kNChunk = 64;
constexpr int kCLen = kN / kNChunk;         // 64

constexpr int TM = 128, TN = 128, BK = 64;  // CTA tile, K-chunk (fp16)
constexpr int SSTR = 72;                    // smem row stride in halves (144 B)
constexpr int PL_ELEMS = TM * SSTR;         // 9216
constexpr int PL_BYTES = PL_ELEMS * 2;      // 18432
constexpr int STAGE_BYTES = 2 * PL_BYTES;   // 36864 (A plane + B plane)
constexpr int NSTAGE = 2;
constexpr int SMEM_BYTES = NSTAGE * STAGE_BYTES;  // 73728 (x2 CTA = 147KB, fits)
}  // namespace

// Device scratch (static; no cudaMalloc allowed)
__device__ __half g_Bu16[(size_t)kM * kQ];
__device__ float2 g_end[kB * kNChunk * kQ];
__device__ float2 g_init[kB * kNChunk * kQ];
__device__ __half g_u16[(size_t)kM * kQ];
__device__ __half g_y16[(size_t)kM * kQ];
__device__ __half g_WB16[kQ * kQ];
__device__ __half g_WC16[kQ * kQ];
__device__ __half g_WD16[kQ * kQ];

// ---------------------------------------------------------------------------
// helpers
// ---------------------------------------------------------------------------
__device__ __forceinline__ uint32_t smem_u32(const void* p) {
    uint32_t a;
    asm("{ .reg .u64 t; cvta.to.shared.u64 t, %1; cvt.u32.u64 %0, t; }" : "=r"(a) : "l"(p));
    return a;
}
__device__ __forceinline__ uint32_t packh(float a, float b) {
    __half2 h = __floats2half2_rn(a, b);
    uint32_t u; memcpy(&u, &h, 4); return u;
}
__device__ __forceinline__ void ldsm4(uint32_t (&r)[4], uint32_t addr) {
    asm volatile("ldmatrix.sync.aligned.m8n8.x4.shared.b16 {%0,%1,%2,%3}, [%4];"
                 : "=r"(r[0]), "=r"(r[1]), "=r"(r[2]), "=r"(r[3]) : "r"(addr));
}
__device__ __forceinline__ void mma16816(float* c, const uint32_t* a, const uint32_t* b) {
    asm volatile(
        "mma.sync.aligned.m16n8k16.row.col.f32.f16.f16.f32 "
        "{%0,%1,%2,%3}, {%4,%5,%6,%7}, {%8,%9}, {%0,%1,%2,%3};"
        : "+f"(c[0]), "+f"(c[1]), "+f"(c[2]), "+f"(c[3])
        : "r"(a[0]), "r"(a[1]), "r"(a[2]), "r"(a[3]), "r"(b[0]), "r"(b[1]));
}
#define CP_COMMIT() asm volatile("cp.async.commit_group;" ::: "memory")
#define CP_WAIT0()  asm volatile("cp.async.wait_group 0;" ::: "memory")

// Issue one stage: A tile (128 x 64 fp16) + B tile (128 x 64 fp16).
// 2048 x 16B transfers, 8 per thread.
__device__ __forceinline__ void cpa_stage(uint32_t sb, const __half* __restrict__ aSrc,
                                          const __half* __restrict__ bSrc, int tid) {
#pragma unroll
    for (int k = 0; k < 4; k++) {
        int t = tid + k * 256;             // 0..1023
        int r = t >> 3, j = t & 7;
        const __half* g = aSrc + (size_t)r * kQ + j * 8;
        uint32_t s = sb + (uint32_t)(r * (SSTR * 2) + j * 16);
        asm volatile("cp.async.ca.shared.global [%0], [%1], 16;" :: "r"(s), "l"(g));
    }
#pragma unroll
    for (int k = 0; k < 4; k++) {
        int t = tid + k * 256;
        int r = t >> 3, j = t & 7;
        const __half* g = bSrc + (size_t)r * kQ + j * 8;
        uint32_t s = sb + PL_BYTES + (uint32_t)(r * (SSTR * 2) + j * 16);
        asm volatile("cp.async.ca.shared.global [%0], [%1], 16;" :: "r"(s), "l"(g));
    }
}

// MMA over one resident stage: warp tile 32(M) x 64(N), 4 k16 steps.
__device__ __forceinline__ void mma_stage(uint32_t sb, float (&acc)[2][8][4],
                                          int lane, int wm, int wn) {
    const int g = lane >> 3, l = lane & 7;
#pragma unroll
    for (int k16 = 0; k16 < 4; k16++) {
        uint32_t afrag[2][4];
        const int acol = k16 * 16 + (g >> 1) * 8;
#pragma unroll
        for (int mt = 0; mt < 2; mt++) {
            const int arow = wm + mt * 16 + (g & 1) * 8 + l;
            ldsm4(afrag[mt], sb + (uint32_t)(arow * SSTR + acol) * 2);
        }
        const int bcol = k16 * 16 + (g & 1) * 8;
#pragma unroll
        for (int np = 0; np < 4; np++) {
            const int brow = wn + np * 16 + (g >> 1) * 8 + l;
            uint32_t bfrag[4];
            ldsm4(bfrag, sb + PL_BYTES + (uint32_t)(brow * SSTR + bcol) * 2);
#pragma unroll
            for (int mt = 0; mt < 2; mt++) {
#pragma unroll
                for (int nt = 0; nt < 2; nt++) {
                    mma16816(acc[mt][np * 2 + nt], afrag[mt], &bfrag[nt * 2]);
                }
            }
        }
    }
}

// ---------------------------------------------------------------------------
// Converter: u (16M elems) + WB/WC/WD (64K each), one kernel.
// ---------------------------------------------------------------------------
__global__ __launch_bounds__(256) void k_cvt(const float* __restrict__ u,
                                             const float* __restrict__ wb,
                                             const float* __restrict__ wc,
                                             const float* __restrict__ wd) {
    const int uN = kM * kQ / 4;
    const int per = kQ * kQ / 4;
    int i = blockIdx.x * blockDim.x + threadIdx.x;
    const float* s;
    __half* d;
    int j;
    if (i < uN) { s = u; d = g_u16; j = i; }
    else {
        int w = i - uN;
        s = (w < per) ? wb : (w < 2 * per ? wc : wd);
        d = (w < per) ? g_WB16 : (w < 2 * per ? g_WC16 : g_WD16);
        j = w % per;
    }
    float4 v = reinterpret_cast<const float4*>(s)[j];
    uint2 o; o.x = packh(v.x, v.y); o.y = packh(v.z, v.w);
    reinterpret_cast<uint2*>(d)[j] = o;
}

// ---------------------------------------------------------------------------
// GEMM1: g_Bu16 = fp16(u16 @ WB16^T + bias)
// ---------------------------------------------------------------------------
__global__ __launch_bounds__(256, 2) void k_mm_bu(const float* __restrict__ bias)
{
    extern __shared__ __half smem[];
    const int tid = threadIdx.x;
    const int bn = blockIdx.x, bm = blockIdx.y;
    const int tileRow = bm * TM;
    const int lane = tid & 31, wid = tid >> 5;
    const int wm = (wid & 3) * 32, wn = (wid >> 2) * 64;
    const uint32_t smb = smem_u32(smem);

    float acc[2][8][4];
#pragma unroll
    for (int a = 0; a < 2; a++)
#pragma unroll
        for (int b = 0; b < 8; b++)
#pragma unroll
            for (int c = 0; c < 4; c++) acc[a][b][c] = 0.0f;

    const __half* aBase = g_u16 + (size_t)tileRow * kQ;
    const __half* bBase = g_WB16 + (size_t)bn * TN * kQ;

    cpa_stage(smb, aBase, bBase, tid); CP_COMMIT();

    constexpr int C = kQ / BK;     // 4
    for (int c = 0; c < C; c++) {
        CP_WAIT0();
        __syncthreads();
        if (c + 1 < C) {
            cpa_stage(smb + ((c + 1) & 1) * STAGE_BYTES,
                      aBase + (c + 1) * BK, bBase + (c + 1) * BK, tid);
            CP_COMMIT();
        }
        mma_stage(smb + (c & 1) * STAGE_BYTES, acc, lane, wm, wn);
    }

    const int r0 = tileRow + wm + (lane >> 2);
    const int cb = bn * TN + wn;
#pragma unroll
    for (int mt = 0; mt < 2; mt++) {
        const int rr = r0 + mt * 16;
#pragma unroll
        for (int nt = 0; nt < 8; nt++) {
            const int cc = cb + nt * 8 + (lane & 3) * 2;
            const float b0 = bias[cc], b1 = bias[cc + 1];
            uint32_t lo = packh(acc[mt][nt][0] + b0, acc[mt][nt][1] + b1);
            uint32_t hi = packh(acc[mt][nt][2] + b0, acc[mt][nt][3] + b1);
            *reinterpret_cast<uint32_t*>(&g_Bu16[(size_t)rr * kQ + cc]) = lo;
            *reinterpret_cast<uint32_t*>(&g_Bu16[(size_t)(rr + 8) * kQ + cc]) = hi;
        }
    }
}

// ---------------------------------------------------------------------------
// GEMM2: h = y16@WC16^T + u16@WD16^T + bC + bD; gelu+glu epilogue,
// residual from u16.
// ---------------------------------------------------------------------------
__global__ __launch_bounds__(256, 2) void k_mm_out(
    const float* __restrict__ bC, const float* __restrict__ bD,
    float* __restrict__ Out)
{
    extern __shared__ __half smem[];
    const int tid = threadIdx.x;
    const int bn = blockIdx.x, bm = blockIdx.y;
    const int tileRow = bm * TM;
    const int lane = tid & 31, wid = tid >> 5;
    const int wm = (wid & 3) * 32, wn = (wid >> 2) * 64;
    const uint32_t smb = smem_u32(smem);

    float acc[2][8][4];
#pragma unroll
    for (int a = 0; a < 2; a++)
#pragma unroll
        for (int b = 0; b < 8; b++)
#pragma unroll
            for (int c = 0; c < 4; c++) acc[a][b][c] = 0.0f;

    constexpr int C = 2 * kQ / BK;   // 8
    auto aPtr = [&](int n) -> const __half* {
        return (n < C / 2 ? g_y16 : g_u16) + (size_t)tileRow * kQ + (n & (C / 2 - 1)) * BK;
    };
    auto bPtr = [&](int n) -> const __half* {
        return (n < C / 2 ? g_WC16 : g_WD16) + (size_t)bn * TN * kQ + (n & (C / 2 - 1)) * BK;
    };

    cpa_stage(smb, aPtr(0), bPtr(0), tid); CP_COMMIT();

    for (int c = 0; c < C; c++) {
        CP_WAIT0();
        __syncthreads();
        if (c + 1 < C) {
            cpa_stage(smb + ((c + 1) & 1) * STAGE_BYTES, aPtr(c + 1), bPtr(c + 1), tid);
            CP_COMMIT();
        }
        mma_stage(smb + (c & 1) * STAGE_BYTES, acc, lane, wm, wn);
    }

    const int r0 = tileRow + wm + (lane >> 2);
    const int cbase = bn * TN + wn;
#pragma unroll
    for (int mt = 0; mt < 2; mt++) {
        const int rr = r0 + mt * 16;
#pragma unroll
        for (int nt = 0; nt < 8; nt++) {
            const int cc = cbase + nt * 8 + (lane & 3) * 2;
            const float b0 = bC[cc] + bD[cc], b1 = bC[cc + 1] + bD[cc + 1];
#pragma unroll
            for (int half = 0; half < 2; half++) {
                const int row = rr + half * 8;
                float h0 = acc[mt][nt][half * 2 + 0] + b0;
                float h1 = acc[mt][nt][half * 2 + 1] + b1;
                __half2 uh = *reinterpret_cast<const __half2*>(&g_u16[(size_t)row * kQ + cc]);
                float2 uv = __half22float2(uh);
                float g0 = 0.5f * h0 * (1.0f + erff(h0 * 0.70710678118654752f));
                float g1 = 0.5f * h1 * (1.0f + erff(h1 * 0.70710678118654752f));
                float o0 = fmaf(g0, 1.0f / (1.0f + __expf(-g0)), uv.x);
                float o1 = fmaf(g1, 1.0f / (1.0f + __expf(-g1)), uv.y);
                float2 w; w.x = o0; w.y = o1;
                *reinterpret_cast<float2*>(&Out[(size_t)row * kQ + cc]) = w;
            }
        }
    }
}

// ---------------------------------------------------------------------------
// Scan pass A: per-chunk end states — 2 channels per thread (__half2 loads)
// ---------------------------------------------------------------------------
__global__ __launch_bounds__(256) void k_scan_ends(const float* __restrict__ A)
{
    int idx = blockIdx.x * blockDim.x + threadIdx.x;   // < kB*kNChunk*kQ/2
    int q2 = idx & (kQ / 2 - 1);                       // column pair 0..127
    int c  = (idx >> 7) & (kNChunk - 1);
    int b  = idx >> 13;
    int qi = q2 * 2;

    float2 av = *reinterpret_cast<const float2*>(&A[qi]);
    float s0   = 1.0f / (1.0f + kDT * kDT * av.x);
    float dts0 = kDT * s0, dsa0 = dts0 * av.x;
    float s1   = 1.0f / (1.0f + kDT * kDT * av.y);
    float dts1 = kDT * s1, dsa1 = dts1 * av.y;

    const __half2* p = reinterpret_cast<const __half2*>(
        g_Bu16 + ((size_t)(b * kN + c * kCLen)) * kQ + qi);
    float x0 = 0.0f, z0 = 0.0f, x1 = 0.0f, z1 = 0.0f;
#pragma unroll 8
    for (int n = 0; n < kCLen; n++) {
        float2 bu = __half22float2(p[(size_t)n * (kQ / 2)]);
        float fx0 = dts0 * bu.x;
        float xn0 = fmaf(s0, x0, fmaf(-dsa0, z0, fx0));
        float zn0 = fmaf(dts0, x0, fmaf(s0, z0, kDT * fx0));
        x0 = xn0; z0 = zn0;
        float fx1 = dts1 * bu.y;
        float xn1 = fmaf(s1, x1, fmaf(-dsa1, z1, fx1));
        float zn1 = fmaf(dts1, x1, fmaf(s1, z1, kDT * fx1));
        x1 = xn1; z1 = zn1;
    }
    float4 o; o.x = x0; o.y = z0; o.z = x1; o.w = z1;
    *reinterpret_cast<float4*>(&g_end[(b * kNChunk + c) * kQ + qi]) = o;
}

// ---------------------------------------------------------------------------
// Scan pass B: PARALLEL chunk-prefix combine (Kogge-Stone affine scan).
// Per-chunk linear part P_chunk = M^kCLen (pre-squared 6x from M).
// ---------------------------------------------------------------------------
__global__ __launch_bounds__(256) void k_scan_combine(const float* __restrict__ A)
{
    __shared__ float2 sb[256];
    const int tid = threadIdx.x;
    const int c = tid & (kNChunk - 1);                 // chunk 0..63
    const int pairIdx = blockIdx.x * 4 + (tid >> 6);   // (b,qi) pair
    const int qi = pairIdx & (kQ - 1);
    const int b  = pairIdx >> 8;

    float av  = A[qi];
    float s   = 1.0f / (1.0f + kDT * kDT * av);
    float dts = kDT * s;
    float dsa = dts * av;

    float p00 = s, p01 = -dsa, p10 = dts, p11 = s;
#pragma unroll
    for (int k = 0; k < 6; k++) {          // M -> M^64 = P_chunk
        float t   = p00 + p11;
        float bc  = p01 * p10;
        float n00 = fmaf(p00, p00, bc);
        float n01 = p01 * t;
        float n10 = p10 * t;
        float n11 = fmaf(p11, p11, bc);
        p00 = n00; p01 = n01; p10 = n10; p11 = n11;
    }

    const int gbase = (b * kNChunk) * kQ + qi;
    float2 v = g_end[gbase + c * kQ];

#pragma unroll
    for (int k = 0; k < 6; k++) {
        const int d = 1 << k;
        sb[tid] = v;
        __syncthreads();
        if (c >= d) {
            float2 lo = sb[tid - d];
            v.x = fmaf(p00, lo.x, fmaf(p01, lo.y, v.x));
            v.y = fmaf(p10, lo.x, fmaf(p11, lo.y, v.y));
        }
        __syncthreads();
        float t   = p00 + p11;
        float bc  = p01 * p10;
        float n00 = fmaf(p00, p00, bc);
        float n01 = p01 * t;
        float n10 = p10 * t;
        float n11 = fmaf(p11, p11, bc);
        p00 = n00; p01 = n01; p10 = n10; p11 = n11;
    }

    sb[tid] = v;
    __syncthreads();
    float2 init = (c == 0) ? make_float2(0.0f, 0.0f) : sb[tid - 1];
    g_init[gbase + c * kQ] = init;
}

// ---------------------------------------------------------------------------
// Scan pass C: re-scan chunks, emit y + y16 — 2 channels per thread
// ---------------------------------------------------------------------------
__global__ __launch_bounds__(256) void k_scan_emit(
    const float* __restrict__ A, float* __restrict__ Yout)
{
    int idx = blockIdx.x * blockDim.x + threadIdx.x;   // < kB*kNChunk*kQ/2
    int q2 = idx & (kQ / 2 - 1);
    int c  = (idx >> 7) & (kNChunk - 1);
    int b  = idx >> 13;
    int qi = q2 * 2;

    float2 av = *reinterpret_cast<const float2*>(&A[qi]);
    float s0   = 1.0f / (1.0f + kDT * kDT * av.x);
    float dts0 = kDT * s0, dsa0 = dts0 * av.x;
    float s1   = 1.0f / (1.0f + kDT * kDT * av.y);
    float dts1 = kDT * s1, dsa1 = dts1 * av.y;

    size_t off = ((size_t)(b * kN + c * kCLen)) * kQ + qi;
    const __half2* p = reinterpret_cast<const __half2*>(g_Bu16 + off);
    float* yp = Yout + off;
    __half2* y16p = reinterpret_cast<__half2*>(g_y16 + off);

    float4 st = *reinterpret_cast<const float4*>(&g_init[(b * kNChunk + c) * kQ + qi]);
    float x0 = st.x, z0 = st.y, x1 = st.z, z1 = st.w;
#pragma unroll 8
    for (int n = 0; n < kCLen; n++) {
        float2 bu = __half22float2(p[(size_t)n * (kQ / 2)]);
        float fx0 = dts0 * bu.x;
        float xn0 = fmaf(s0, x0, fmaf(-dsa0, z0, fx0));
        float zn0 = fmaf(dts0, x0, fmaf(s0, z0, kDT * fx0));
        x0 = xn0; z0 = zn0;
        float fx1 = dts1 * bu.y;
        float xn1 = fmaf(s1, x1, fmaf(-dsa1, z1, fx1));
        float zn1 = fmaf(dts1, x1, fmaf(s1, z1, kDT * fx1));
        x1 = xn1; z1 = zn1;
        float2 yo; yo.x = z0; yo.y = z1;
        *reinterpret_cast<float2*>(yp + (size_t)n * kQ) = yo;
        y16p[(size_t)n * (kQ / 2)] = __floats2half2_rn(z0, z1);
    }
}

// ---------------------------------------------------------------------------
// Launch
// ---------------------------------------------------------------------------
extern "C" void kernel_launch(void* const* d_in, const int* in_sizes, int n_in,
                              void* d_out, int out_size)
{
    const float* u  = (const float*)d_in[0];
    const float* a  = (const float*)d_in[1];
    const float* WB = (const float*)d_in[2];
    const float* bB = (const float*)d_in[3];
    const float* WC = (const float*)d_in[4];
    const float* bC = (const float*)d_in[5];
    const float* WD = (const float*)d_in[6];
    const float* bD = (const float*)d_in[7];

    float* out  = (float*)d_out;
    float* yout = out + (size_t)out_size / 2;

    static bool attr_done = false;
    if (!attr_done) {
        cudaFuncSetAttribute(k_mm_bu,  cudaFuncAttributeMaxDynamicSharedMemorySize, SMEM_BYTES);
        cudaFuncSetAttribute(k_mm_out, cudaFuncAttributeMaxDynamicSharedMemorySize, SMEM_BYTES);
        attr_done = true;
    }

    const int cvtTotal = kM * kQ / 4 + 3 * kQ * kQ / 4;
    k_cvt<<<cvtTotal / 256, 256>>>(u, WB, WC, WD);

    dim3 grid(kQ / TN, kM / TM);                // (2, 512)
    k_mm_bu<<<grid, 256, SMEM_BYTES>>>(bB);

    int scanPairs = kB * kNChunk * kQ / 2;      // 131072
    k_scan_ends<<<scanPairs / 256, 256>>>(a);
    k_scan_combine<<<(kB * kQ * kNChunk) / 256, 256>>>(a);   // 1024 blocks
    k_scan_emit<<<scanPairs / 256, 256>>>(a, yout);

    k_mm_out<<<grid, 256, SMEM_BYTES>>>(bC, bD, out);
}